// round 14
// baseline (speedup 1.0000x reference)
#include <cuda_runtime.h>
#include <cuda_bf16.h>
#include <string.h>
#include <math.h>

// ---------------- problem constants ----------------
#define EID   30000
#define EMB   256
#define HID   512
#define SRC_T 128
#define TRG_T 50
#define B     64
#define G3    (3*HID)          // 1536

// ---------------- device state ----------------
__device__ float g_hT[2 * HID * B];                    // hidden, transposed [j][b], double buffered
__device__ float g_giEnc[(size_t)SRC_T * G3 * B];      // encoder gi, [t][j][b] (incl. b_ih)
__device__ float g_A[8 * G3 * B];                      // gh partials, [p][j][b]
__device__ float g_Bp[5 * G3 * B];                     // gi partials (decoder), [p][j][b]
__device__ float g_C[12 * B * HID];                    // r1 partials, [p][b][j]
__device__ float g_logits[(size_t)B * EID];
__device__ float g_pm[B * 5], g_ps[B * 5];
__device__ int   g_pi[B * 5];
__device__ float g_rate[B];
__device__ int   g_idx[B];

// ---------------- packed fp32 FMA (sm_100+) ----------------
__device__ __forceinline__ float2 ffma2(float2 a, float2 b, float2 c) {
    unsigned long long ua, ub, uc, ud;
    memcpy(&ua, &a, 8); memcpy(&ub, &b, 8); memcpy(&uc, &c, 8);
    asm("fma.rn.f32x2 %0, %1, %2, %3;" : "=l"(ud) : "l"(ua), "l"(ub), "l"(uc));
    float2 d; memcpy(&d, &ud, 8); return d;
}

__device__ __forceinline__ float sigf(float x) { return 1.f / (1.f + expf(-x)); }

// ---------------- 64x64 micro-kernel (4 pairs x 4 cols / thread, 128 thr) ----------------
__device__ __forceinline__ void mm64_4x4(const float* __restrict__ xs,
                                         const float* __restrict__ ws,
                                         int bpg, int cg, float2 acc[4][4]) {
    #pragma unroll 4
    for (int k = 0; k < 64; k++) {
        float2 xv[4];
        #pragma unroll
        for (int i = 0; i < 4; i++)
            xv[i] = *reinterpret_cast<const float2*>(&xs[k * 66 + 2 * (bpg + 8 * i)]);
        #pragma unroll
        for (int c = 0; c < 4; c++) {
            float w = ws[(cg * 4 + c) * 65 + k];
            float2 wp = make_float2(w, w);
            #pragma unroll
            for (int i = 0; i < 4; i++) acc[i][c] = ffma2(xv[i], wp, acc[i][c]);
        }
    }
}

// store to transposed partial layout [j][b]
__device__ __forceinline__ void store_T(float* __restrict__ dst, int n0,
                                        int bpg, int cg, float2 acc[4][4]) {
    #pragma unroll
    for (int c = 0; c < 4; c++) {
        int j3 = n0 + cg * 4 + c;
        #pragma unroll
        for (int i = 0; i < 4; i++) {
            int p = bpg + 8 * i;
            dst[j3 * 64 + 2 * p]     = acc[i][c].x;
            dst[j3 * 64 + 2 * p + 1] = acc[i][c].y;
        }
    }
}

// store to [b][N] layout (r1 partials)
__device__ __forceinline__ void store_BN(float* __restrict__ dst, int N, int n0,
                                         int bpg, int cg, float2 acc[4][4]) {
    #pragma unroll
    for (int c = 0; c < 4; c++) {
        int n = n0 + cg * 4 + c;
        #pragma unroll
        for (int i = 0; i < 4; i++) {
            int p = bpg + 8 * i;
            dst[(size_t)(2 * p) * N + n]     = acc[i][c].x;
            dst[(size_t)(2 * p + 1) * N + n] = acc[i][c].y;
        }
    }
}

// ---------------- encoder gh GEMM: grid (24, 4), 2 k-tiles per block ----------------
__global__ __launch_bounds__(128)
void enc_gemm(const float* __restrict__ h, const float* __restrict__ W_hh)
{
    __shared__ float xs[64 * 66];
    __shared__ float ws[64 * 65];
    const int tid = threadIdx.x;
    const int jn = blockIdx.x, jk = blockIdx.y;   // jk < 4
    const int n0 = jn * 64, k0 = jk * 128;
    const int bpg = tid & 7, cg = tid >> 3;

    float2 acc[4][4];
    #pragma unroll
    for (int i = 0; i < 4; i++)
        #pragma unroll
        for (int c = 0; c < 4; c++) acc[i][c] = make_float2(0.f, 0.f);

    for (int kt = k0; kt < k0 + 128; kt += 64) {
        __syncthreads();
        for (int e = tid; e < 4096; e += 128) {
            int k = e >> 6, b = e & 63;
            xs[k * 66 + b] = h[(kt + k) * 64 + b];
        }
        for (int e = tid; e < 4096; e += 128) {
            int nl = e >> 6, k = e & 63;
            ws[nl * 65 + k] = W_hh[(size_t)(n0 + nl) * HID + kt + k];
        }
        __syncthreads();
        mm64_4x4(xs, ws, bpg, cg, acc);
    }
    store_T(g_A + (size_t)jk * G3 * 64, n0, bpg, cg, acc);
}

// ---------------- decoder gi+gh GEMM with fused input gather: grid (24, 13) [R11 verbatim] ----------------
__global__ __launch_bounds__(128)
void dec_gemm_both(const float* __restrict__ h,
                   const float* __restrict__ emb_dec,
                   const float* __restrict__ W_ih, const float* __restrict__ W_hh)
{
    __shared__ float xs[64 * 66];
    __shared__ float ws[64 * 65];
    const int tid = threadIdx.x;
    const int jn = blockIdx.x, jk = blockIdx.y;
    const int n0 = jn * 64;
    const int bpg = tid & 7, cg = tid >> 3;

    if (jk < 5) {
        int kb = jk * 64;
        for (int e = tid; e < 4096; e += 128) {
            int b = e >> 6, kl = e & 63, kk = kb + kl;
            float v = 0.f;
            if (kk < EMB)       v = emb_dec[(size_t)g_idx[b] * EMB + kk];
            else if (kk == EMB) v = g_rate[b];
            xs[kl * 66 + b] = v;
        }
        for (int e = tid; e < 4096; e += 128) {
            int nl = e >> 6, k = e & 63, kk = kb + k;
            ws[nl * 65 + k] = (kk < EMB + 1) ? W_ih[(size_t)(n0 + nl) * (EMB + 1) + kk] : 0.f;
        }
    } else {
        int kb = (jk - 5) * 64;
        for (int e = tid; e < 4096; e += 128) {
            int k = e >> 6, b = e & 63;
            xs[k * 66 + b] = h[(kb + k) * 64 + b];
        }
        for (int e = tid; e < 4096; e += 128) {
            int nl = e >> 6, k = e & 63;
            ws[nl * 65 + k] = W_hh[(size_t)(n0 + nl) * HID + kb + k];
        }
    }
    __syncthreads();

    float2 acc[4][4];
    #pragma unroll
    for (int i = 0; i < 4; i++)
        #pragma unroll
        for (int c = 0; c < 4; c++) acc[i][c] = make_float2(0.f, 0.f);
    mm64_4x4(xs, ws, bpg, cg, acc);
    float* dst = (jk < 5) ? (g_Bp + (size_t)jk * G3 * 64) : (g_A + (size_t)(jk - 5) * G3 * 64);
    store_T(dst, n0, bpg, cg, acc);
}

// ---------------- GRU gate combine [R11 verbatim] ----------------
__global__ void combine_T(const float* __restrict__ Ap, int nA,
                          const float* __restrict__ Bsrc, int nB,
                          const float* __restrict__ b_ih, const float* __restrict__ b_hh,
                          const float* __restrict__ hin, float* __restrict__ hout,
                          const int* __restrict__ src_len, int t)
{
    int i = blockIdx.x * blockDim.x + threadIdx.x;   // 128 x 256 = 32768
    if (i >= B * HID) return;
    const int j = i >> 6, b = i & 63;

    float ar = b_hh[j], az = b_hh[j + 512], an = b_hh[j + 1024];
    #pragma unroll 4
    for (int p = 0; p < nA; p++) {
        const float* a = Ap + (size_t)p * G3 * 64;
        ar += a[j * 64 + b]; az += a[(j + 512) * 64 + b]; an += a[(j + 1024) * 64 + b];
    }
    float br, bz, bn;
    if (nB == 0) {
        br = Bsrc[j * 64 + b]; bz = Bsrc[(j + 512) * 64 + b]; bn = Bsrc[(j + 1024) * 64 + b];
    } else {
        br = b_ih[j]; bz = b_ih[j + 512]; bn = b_ih[j + 1024];
        #pragma unroll 4
        for (int p = 0; p < nB; p++) {
            const float* a = Bsrc + (size_t)p * G3 * 64;
            br += a[j * 64 + b]; bz += a[(j + 512) * 64 + b]; bn += a[(j + 1024) * 64 + b];
        }
    }
    float r = sigf(ar + br);
    float z = sigf(az + bz);
    float n = tanhf(bn + r * an);
    float ho = hin[j * 64 + b];
    float hv = (1.f - z) * n + z * ho;
    if (src_len && !(t < src_len[b])) hv = ho;
    hout[j * 64 + b] = hv;
}

// ---------------- logits GEMM: grid 313 x 192 thr, 2 pairs x 8 cols / thread ----------------
__global__ __launch_bounds__(192)
void logits_gemm(const float* __restrict__ hT, const float* __restrict__ W_eid,
                 const float* __restrict__ b_eid, float* __restrict__ Lout)
{
    __shared__ float xs[64 * 66];
    __shared__ __align__(16) float ws[96 * 68];     // stride 68 -> 16B-aligned rows
    const int tid = threadIdx.x;
    const int n0 = blockIdx.x * 96;
    const int bp = tid & 15;        // pair group: pairs bp, bp+16
    const int cg = tid >> 4;        // 12 col-groups x 8 cols

    float2 acc[2][8];
    #pragma unroll
    for (int i = 0; i < 2; i++)
        #pragma unroll
        for (int c = 0; c < 8; c++) acc[i][c] = make_float2(0.f, 0.f);

    for (int kt = 0; kt < HID; kt += 64) {
        __syncthreads();
        for (int e = tid; e < 4096; e += 192) {
            int k = e >> 6, b = e & 63;
            xs[k * 66 + b] = hT[(kt + k) * 64 + b];
        }
        for (int e = tid; e < 96 * 64; e += 192) {
            int nl = e >> 6, k = e & 63;
            int n = n0 + nl;
            ws[nl * 68 + k] = (n < EID) ? W_eid[(size_t)n * HID + kt + k] : 0.f;
        }
        __syncthreads();

        #pragma unroll 2
        for (int k4 = 0; k4 < 64; k4 += 4) {
            float4 wv[8];
            #pragma unroll
            for (int c = 0; c < 8; c++)
                wv[c] = *reinterpret_cast<const float4*>(&ws[(cg * 8 + c) * 68 + k4]);
            #pragma unroll
            for (int q = 0; q < 4; q++) {
                float2 x0 = *reinterpret_cast<const float2*>(&xs[(k4 + q) * 66 + 2 * bp]);
                float2 x1 = *reinterpret_cast<const float2*>(&xs[(k4 + q) * 66 + 2 * (bp + 16)]);
                #pragma unroll
                for (int c = 0; c < 8; c++) {
                    float w = (q == 0) ? wv[c].x : (q == 1) ? wv[c].y
                            : (q == 2) ? wv[c].z : wv[c].w;
                    float2 wp = make_float2(w, w);
                    acc[0][c] = ffma2(x0, wp, acc[0][c]);
                    acc[1][c] = ffma2(x1, wp, acc[1][c]);
                }
            }
        }
    }

    #pragma unroll
    for (int c = 0; c < 8; c++) {
        int n = n0 + cg * 8 + c;
        if (n >= EID) continue;
        float bv = b_eid[n];
        Lout[(size_t)(2 * bp) * EID + n]            = acc[0][c].x + bv;
        Lout[(size_t)(2 * bp + 1) * EID + n]        = acc[0][c].y + bv;
        Lout[(size_t)(2 * (bp + 16)) * EID + n]     = acc[1][c].x + bv;
        Lout[(size_t)(2 * (bp + 16) + 1) * EID + n] = acc[1][c].y + bv;
    }
}

// ---------------- r1 GEMM with fused concat gather: grid (8, 12) [R11 verbatim] ----------------
__global__ __launch_bounds__(128)
void r1_gemm_fused(const float* __restrict__ emb_mt, const float* __restrict__ hT,
                   const float* __restrict__ W_r1, float* __restrict__ C)
{
    __shared__ float xs[64 * 66];
    __shared__ float ws[64 * 65];
    const int tid = threadIdx.x, jn = blockIdx.x, jk = blockIdx.y;
    const int n0 = jn * 64, k0 = jk * 64;
    const int bpg = tid & 7, cg = tid >> 3;

    if (k0 < EMB) {
        for (int e = tid; e < 4096; e += 128) {
            int b = e >> 6, kl = e & 63;
            xs[kl * 66 + b] = emb_mt[(size_t)g_idx[b] * EMB + k0 + kl];
        }
    } else {
        for (int e = tid; e < 4096; e += 128) {
            int k = e >> 6, b = e & 63;
            xs[k * 66 + b] = hT[(k0 - EMB + k) * 64 + b];
        }
    }
    for (int e = tid; e < 4096; e += 128) {
        int nl = e >> 6, k = e & 63;
        ws[nl * 65 + k] = W_r1[(size_t)(n0 + nl) * (EMB + HID) + k0 + k];
    }
    __syncthreads();

    float2 acc[4][4];
    #pragma unroll
    for (int i = 0; i < 4; i++)
        #pragma unroll
        for (int c = 0; c < 4; c++) acc[i][c] = make_float2(0.f, 0.f);
    mm64_4x4(xs, ws, bpg, cg, acc);
    store_BN(C + (size_t)jk * B * HID, HID, n0, bpg, cg, acc);
}

// ---------------- softmax partials: 320 blocks = 64 b x 5 slices of 6000 [R11 verbatim] ----------------
__global__ void softmax_partials(void)
{
    __shared__ float rm[256], rs[256];
    __shared__ int   ri[256];
    const int b = blockIdx.x & 63, sl = blockIdx.x >> 6, tid = threadIdx.x;
    const float* L = g_logits + (size_t)b * EID;
    const int n0 = sl * 6000;

    float m = -3.4e38f, sum = 0.f; int ix = 0x7fffffff;
    for (int n = n0 + tid; n < n0 + 6000; n += 256) {
        float v = L[n];
        if (v > m) { sum = sum * expf(m - v) + 1.f; m = v; ix = n; }
        else       sum += expf(v - m);
    }
    rm[tid] = m; rs[tid] = sum; ri[tid] = ix;
    __syncthreads();
    for (int st = 128; st; st >>= 1) {
        if (tid < st) {
            float m1 = rm[tid], m2 = rm[tid + st], s1 = rs[tid], s2 = rs[tid + st];
            int i1 = ri[tid], i2 = ri[tid + st];
            float M = fmaxf(m1, m2);
            rs[tid] = s1 * expf(m1 - M) + s2 * expf(m2 - M);
            rm[tid] = M;
            ri[tid] = (m2 > m1) ? i2 : ((m1 > m2) ? i1 : min(i1, i2));
        }
        __syncthreads();
    }
    if (tid == 0) {
        g_pm[b * 5 + sl] = rm[0]; g_ps[b * 5 + sl] = rs[0]; g_pi[b * 5 + sl] = ri[0];
    }
}

// merge the 5 per-slice partials of batch b -> (lse, first-argmax)
__device__ __forceinline__ void merge5(int b, float& lse, int& amax) {
    float M = -3.4e38f, S = 0.f; int I = 0x7fffffff;
    #pragma unroll
    for (int sl = 0; sl < 5; sl++) {
        float m2 = g_pm[b * 5 + sl], s2 = g_ps[b * 5 + sl];
        int i2 = g_pi[b * 5 + sl];
        float Mn = fmaxf(M, m2);
        S = S * expf(M - Mn) + s2 * expf(m2 - Mn);
        I = (m2 > M) ? i2 : ((M > m2) ? I : min(I, i2));
        M = Mn;
    }
    lse = M + logf(S);
    amax = I;
}

// ---------------- softmax write + argmax publish: 320 blocks [R11 verbatim] ----------------
__global__ void softmax_write(float* __restrict__ out, int row)
{
    const int b = blockIdx.x & 63, sl = blockIdx.x >> 6, tid = threadIdx.x;
    float lse; int amax; merge5(b, lse, amax);
    const float* L = g_logits + (size_t)b * EID;
    float* O = out + ((size_t)row * B + b) * EID;
    for (int n = sl * 6000 + tid; n < sl * 6000 + 6000; n += 256) O[n] = L[n] - lse;
    if (sl == 0 && tid == 0) g_idx[b] = amax;
}

// ---------------- rate head finish [R11 verbatim] ----------------
__global__ void rate_head(const float* __restrict__ C, const float* __restrict__ b_r1,
                          const float* __restrict__ W_r2, const float* __restrict__ b_r2,
                          float* __restrict__ outRate, int row, float* __restrict__ rateState)
{
    const int b = blockIdx.x, j = threadIdx.x;   // 512 threads
    float v = b_r1[j];
    #pragma unroll
    for (int p = 0; p < 12; p++) v += C[((size_t)p * B + b) * HID + j];
    v = fmaxf(v, 0.f) * W_r2[j];
    __shared__ float sv[512];
    sv[j] = v; __syncthreads();
    for (int s = 256; s; s >>= 1) { if (j < s) sv[j] += sv[j + s]; __syncthreads(); }
    if (j == 0) {
        float pr = sigf(sv[0] + b_r2[0]);
        outRate[(size_t)row * B + b] = pr;
        rateState[b] = pr;
    }
}

// ---------------- prep kernels [R11 verbatim] ----------------
__global__ void init_state(const int* __restrict__ trg_eid, const float* __restrict__ trg_rate)
{
    int i = blockIdx.x * 256 + threadIdx.x;
    if (i < HID * B) g_hT[i] = 0.f;
    if (i < B) { g_idx[i] = trg_eid[i]; g_rate[i] = trg_rate[i]; }
}

// gi[t][j][b] = b_ih[j] + sum_k src[t][b][k] * W_ih[j][k]
__global__ void enc_gi(const float* __restrict__ src, const float* __restrict__ W_ih,
                       const float* __restrict__ b_ih)
{
    const int j = blockIdx.x * 4 + (threadIdx.x >> 6);
    const int b = threadIdx.x & 63;
    const int t = blockIdx.y;
    const float* x = src + ((size_t)t * 64 + b) * 3;
    float v = b_ih[j] + x[0] * W_ih[j * 3] + x[1] * W_ih[j * 3 + 1] + x[2] * W_ih[j * 3 + 2];
    g_giEnc[((size_t)t * G3 + j) * 64 + b] = v;
}

// ---------------- host launcher ----------------
extern "C" void kernel_launch(void* const* d_in, const int* in_sizes, int n_in,
                              void* d_out, int out_size)
{
    const float* src      = (const float*)d_in[0];
    const int*   src_len  = (const int*)  d_in[1];
    const int*   trg_eid  = (const int*)  d_in[2];
    const float* trg_rate = (const float*)d_in[3];
    const float* W_ih_enc = (const float*)d_in[4];
    const float* W_hh_enc = (const float*)d_in[5];
    const float* b_ih_enc = (const float*)d_in[6];
    const float* b_hh_enc = (const float*)d_in[7];
    const float* emb_dec  = (const float*)d_in[8];
    const float* W_ih_dec = (const float*)d_in[9];
    const float* W_hh_dec = (const float*)d_in[10];
    const float* b_ih_dec = (const float*)d_in[11];
    const float* b_hh_dec = (const float*)d_in[12];
    const float* emb_mt   = (const float*)d_in[13];
    const float* W_eid    = (const float*)d_in[14];
    const float* b_eid    = (const float*)d_in[15];
    const float* W_r1     = (const float*)d_in[16];
    const float* b_r1     = (const float*)d_in[17];
    const float* W_r2     = (const float*)d_in[18];
    const float* b_r2     = (const float*)d_in[19];
    float* out = (float*)d_out;
    float* out_rate = out + (size_t)TRG_T * B * EID;

    float *hT, *giEnc, *A, *Bp, *C, *logits, *rate;
    cudaGetSymbolAddress((void**)&hT,     g_hT);
    cudaGetSymbolAddress((void**)&giEnc,  g_giEnc);
    cudaGetSymbolAddress((void**)&A,      g_A);
    cudaGetSymbolAddress((void**)&Bp,     g_Bp);
    cudaGetSymbolAddress((void**)&C,      g_C);
    cudaGetSymbolAddress((void**)&logits, g_logits);
    cudaGetSymbolAddress((void**)&rate,   g_rate);
    float* hbuf[2] = { hT, hT + HID * B };

    // zero output row 0 (eid + rate)
    cudaMemsetAsync(out, 0, (size_t)B * EID * sizeof(float), 0);
    cudaMemsetAsync(out_rate, 0, B * sizeof(float), 0);

    init_state<<<128, 256>>>(trg_eid, trg_rate);
    enc_gi<<<dim3(384, SRC_T), 256>>>(src, W_ih_enc, b_ih_enc);

    // ---------- encoder: 128 masked GRU steps (2 nodes/step, k-split 4) ----------
    for (int t = 0; t < SRC_T; t++) {
        enc_gemm<<<dim3(24, 4), 128>>>(hbuf[t & 1], W_hh_enc);
        combine_T<<<128, 256>>>(A, 4, giEnc + (size_t)t * G3 * 64, 0,
                                nullptr, b_hh_enc, hbuf[t & 1], hbuf[(t + 1) & 1],
                                src_len, t);
    }

    // ---------- decoder: 49 autoregressive steps (7 nodes/step) ----------
    for (int s = 0; s < TRG_T - 1; s++) {
        const int pi = s & 1, po = (s + 1) & 1;
        dec_gemm_both<<<dim3(24, 13), 128>>>(hbuf[pi], emb_dec, W_ih_dec, W_hh_dec);
        combine_T<<<128, 256>>>(A, 8, Bp, 5, b_ih_dec, b_hh_dec,
                                hbuf[pi], hbuf[po], nullptr, 0);
        // big output projection: retiled inner loop (2 pairs x 8 cols, LDS.128 weights)
        logits_gemm<<<313, 192>>>(hbuf[po], W_eid, b_eid, logits);
        softmax_partials<<<320, 256>>>();
        softmax_write<<<320, 256>>>(out, s + 1);
        r1_gemm_fused<<<dim3(8, 12), 128>>>(emb_mt, hbuf[po], W_r1, C);
        rate_head<<<64, 512>>>(C, b_r1, W_r2, b_r2, out_rate, s + 1, rate);
    }
}